// round 14
// baseline (speedup 1.0000x reference)
#include <cuda_runtime.h>
#include <cuda_bf16.h>
#include <cstdint>
#include <math.h>

// ---------------------------------------------------------------------------
// Shapes (fixed): tokens T=8192, H=4096, I=14336
// ---------------------------------------------------------------------------
#define HDIM 4096
#define IDIM 14336
#define TH   0.5f
#define BAND 0.008f                 // borderline-mask band on |u*a| around TH

#define KT    16                    // k per smem chunk (16 bf16 = 32 B/row)
#define ROWB  48                    // smem row stride bytes (32 data + 16 pad)
#define NSTG  4

// bf16 2-limb planes (hi + lo) for all GEMM operands and the activation
__device__ __nv_bfloat16 g_xh [33554432ull],  g_xl [33554432ull];    // x
__device__ __nv_bfloat16 g_wuh[58720256ull],  g_wul[58720256ull];    // w_up
__device__ __nv_bfloat16 g_wgh[58720256ull],  g_wgl[58720256ull];    // w_gate
__device__ __nv_bfloat16 g_wdh[58720256ull],  g_wdl[58720256ull];    // w_down
__device__ __nv_bfloat16 g_ah [117440512ull], g_al [117440512ull];   // act

// ---------------------------------------------------------------------------
// helpers
// ---------------------------------------------------------------------------
__device__ __forceinline__ uint32_t smem_u32(const void* p) {
    uint32_t a;
    asm("{ .reg .u64 t; cvta.to.shared.u64 t, %1; cvt.u32.u64 %0, t; }" : "=r"(a) : "l"(p));
    return a;
}
__device__ __forceinline__ void cp_async16(uint32_t dst, const void* src) {
    asm volatile("cp.async.cg.shared.global [%0], [%1], 16;" :: "r"(dst), "l"(src) : "memory");
}
__device__ __forceinline__ void cp_commit() {
    asm volatile("cp.async.commit_group;" ::: "memory");
}
template <int N> __device__ __forceinline__ void cp_wait() {
    asm volatile("cp.async.wait_group %0;" :: "n"(N) : "memory");
}

// m16n8k16 bf16 mma, fp32 accumulate
__device__ __forceinline__ void mmabf(float* c, const uint32_t* a, const uint32_t* b) {
    asm volatile(
        "mma.sync.aligned.m16n8k16.row.col.f32.bf16.bf16.f32 "
        "{%0,%1,%2,%3}, {%4,%5,%6,%7}, {%8,%9}, {%0,%1,%2,%3};"
        : "+f"(c[0]), "+f"(c[1]), "+f"(c[2]), "+f"(c[3])
        : "r"(a[0]), "r"(a[1]), "r"(a[2]), "r"(a[3]), "r"(b[0]), "r"(b[1]));
}

__device__ __forceinline__ float masked_silu(float u, float g, float a) {
    float o = 0.f;
    if (fabsf(u * a) >= TH) o = u * (g / (1.f + expf(-g)));
    return o;
}

// split v into hi/lo bf16 limbs (v ~= hi + lo)
__device__ __forceinline__ void bsplit(float v, __nv_bfloat16& h, __nv_bfloat16& l) {
    h = __float2bfloat16_rn(v);
    l = __float2bfloat16_rn(v - __bfloat162float(h));
}
__device__ __forceinline__ uint32_t bpack(__nv_bfloat16 lo, __nv_bfloat16 hi) {
    return (uint32_t)__bfloat16_as_ushort(lo) | ((uint32_t)__bfloat16_as_ushort(hi) << 16);
}

// exact fp32 dot(x_row, wu_row) over HDIM, warp-cooperative
__device__ __noinline__ float warp_dot(const float* __restrict__ xr,
                                       const float* __restrict__ wr, int lane) {
    const float4* x4 = (const float4*)xr;
    const float4* w4 = (const float4*)wr;
    float s = 0.f;
#pragma unroll 4
    for (int i = lane; i < HDIM / 4; i += 32) {
        float4 a = x4[i], b = w4[i];
        s = fmaf(a.x, b.x, s); s = fmaf(a.y, b.y, s);
        s = fmaf(a.z, b.z, s); s = fmaf(a.w, b.w, s);
    }
#pragma unroll
    for (int off = 16; off; off >>= 1) s += __shfl_xor_sync(0xffffffffu, s, off);
    return s;
}

// ---------------------------------------------------------------------------
// prep: fp32 -> 2-limb bf16 planes (one merged launch for x, wg, wu, wd)
// ---------------------------------------------------------------------------
#define N4X (8192 * HDIM / 4)       // 8388608 float4s
#define N4W (IDIM * HDIM / 4)       // 14680064

__device__ __forceinline__ void prep4(const float* __restrict__ src,
                                      __nv_bfloat16* __restrict__ hp,
                                      __nv_bfloat16* __restrict__ lp, size_t i) {
    float4 v = ((const float4*)src)[i];
    __nv_bfloat16 h0, h1, h2, h3, l0, l1, l2, l3;
    bsplit(v.x, h0, l0); bsplit(v.y, h1, l1);
    bsplit(v.z, h2, l2); bsplit(v.w, h3, l3);
    uint2 ho, lo;
    ho.x = bpack(h0, h1); ho.y = bpack(h2, h3);
    lo.x = bpack(l0, l1); lo.y = bpack(l2, l3);
    ((uint2*)hp)[i] = ho;
    ((uint2*)lp)[i] = lo;
}

__global__ __launch_bounds__(256)
void prep_all(const float* __restrict__ x,  const float* __restrict__ wg,
              const float* __restrict__ wu, const float* __restrict__ wd)
{
    long long i = (long long)blockIdx.x * blockDim.x + threadIdx.x;
    if (i < N4X)                        prep4(x,  g_xh,  g_xl,  (size_t)i);
    else if (i < (long long)N4X + N4W)  prep4(wg, g_wgh, g_wgl, (size_t)(i - N4X));
    else if (i < (long long)N4X + 2LL * N4W) prep4(wu, g_wuh, g_wul, (size_t)(i - N4X - N4W));
    else if (i < (long long)N4X + 3LL * N4W) prep4(wd, g_wdh, g_wdl, (size_t)(i - N4X - 2LL * N4W));
}

// ---------------------------------------------------------------------------
// P1: up/gate bf16 2-limb fused GEMM -> mask (band-recomputed) -> act limbs
// CTA 128x64, 4 warps (2x2) @ warp 64x32. KT=16, 4-stage, 2 CTAs/SM.
// smem: 512 plane-rows x 48 B: x_hi[0,128) x_lo[128,256) wu_hi[256,320)
//       wu_lo[320,384) wg_hi[384,448) wg_lo[448,512)
// ---------------------------------------------------------------------------
#define P1_STAGE (512 * ROWB)       // 24576 B
#define P1_SMEM  (NSTG * P1_STAGE)  // 98304 B

__global__ __launch_bounds__(128, 2)
void p1_kernel(const float* __restrict__ ag,
               const float* __restrict__ x_orig, const float* __restrict__ wu_orig)
{
    extern __shared__ char smc[];
    const uint32_t sb = smem_u32(smc);

    const int per = 16 * 224;
    const int grp = blockIdx.x / per;
    const int w   = blockIdx.x % per;
    const int m0  = (grp * 16 + (w % 16)) * 128;
    const int n0  = (w / 16) * 64;

    const int tid  = threadIdx.x;
    const int wid  = tid >> 5;
    const int lane = tid & 31;
    const int wm   = wid >> 1;      // 0..1 (M, 64 rows)
    const int wn   = wid & 1;       // 0..1 (N, 32 cols)
    const int ar   = lane >> 2;
    const int ac   = lane & 3;
    const int koA  = 4 * ac;

    float upc[4][4][4];
    float gtc[4][4][4];
#pragma unroll
    for (int t = 0; t < 4; ++t)
#pragma unroll
        for (int u = 0; u < 4; ++u)
#pragma unroll
            for (int q = 0; q < 4; ++q) { upc[t][u][q] = 0.f; gtc[t][u][q] = 0.f; }

    const int NCH = HDIM / KT;      // 256

    auto load_chunk = [&](int ch) {
        const uint32_t so = sb + (uint32_t)((ch & (NSTG - 1)) * P1_STAGE);
        const int kb = ch * KT;     // bf16 element offset
#pragma unroll
        for (int q = 0; q < 8; ++q) {
            int lin  = q * 128 + tid;
            int gran = lin >> 9;            // 0/1: which 16B granule of the row
            int prow = lin & 511;
            const __nv_bfloat16* p;
            size_t roff;
            if (prow < 128)      { p = g_xh;  roff = (size_t)(m0 + prow) * HDIM; }
            else if (prow < 256) { p = g_xl;  roff = (size_t)(m0 + prow - 128) * HDIM; }
            else if (prow < 320) { p = g_wuh; roff = (size_t)(n0 + prow - 256) * HDIM; }
            else if (prow < 384) { p = g_wul; roff = (size_t)(n0 + prow - 320) * HDIM; }
            else if (prow < 448) { p = g_wgh; roff = (size_t)(n0 + prow - 384) * HDIM; }
            else                 { p = g_wgl; roff = (size_t)(n0 + prow - 448) * HDIM; }
            cp_async16(so + (uint32_t)(prow * ROWB + gran * 16),
                       p + roff + kb + gran * 8);
        }
        cp_commit();
    };

    load_chunk(0);
    load_chunk(1);
    load_chunk(2);

    for (int ch = 0; ch < NCH; ++ch) {
        cp_wait<2>();
        __syncthreads();
        if (ch + 3 < NCH) load_chunk(ch + 3);
        else cp_commit();

        const char* st = smc + (ch & (NSTG - 1)) * P1_STAGE;

        // A fragments (x), hi + lo limbs
        uint32_t ah4[4][4], al4[4][4];
#pragma unroll
        for (int t = 0; t < 4; ++t) {
            const int r0 = (wm * 64 + t * 16 + ar) * ROWB;
            const int r1 = r0 + 8 * ROWB;
            ah4[t][0] = *(const uint32_t*)(st + r0 + koA);
            ah4[t][1] = *(const uint32_t*)(st + r1 + koA);
            ah4[t][2] = *(const uint32_t*)(st + r0 + koA + 16);
            ah4[t][3] = *(const uint32_t*)(st + r1 + koA + 16);
            al4[t][0] = *(const uint32_t*)(st + 6144 + r0 + koA);
            al4[t][1] = *(const uint32_t*)(st + 6144 + r1 + koA);
            al4[t][2] = *(const uint32_t*)(st + 6144 + r0 + koA + 16);
            al4[t][3] = *(const uint32_t*)(st + 6144 + r1 + koA + 16);
        }
        // up GEMM: wu limbs
        {
            uint32_t bh[4][2], bl[4][2];
#pragma unroll
            for (int u = 0; u < 4; ++u) {
                const int nr = (wn * 32 + u * 8 + ar) * ROWB;
                bh[u][0] = *(const uint32_t*)(st + 12288 + nr + koA);
                bh[u][1] = *(const uint32_t*)(st + 12288 + nr + koA + 16);
                bl[u][0] = *(const uint32_t*)(st + 15360 + nr + koA);
                bl[u][1] = *(const uint32_t*)(st + 15360 + nr + koA + 16);
            }
#pragma unroll
            for (int t = 0; t < 4; ++t)
#pragma unroll
                for (int u = 0; u < 4; ++u) {
                    mmabf(upc[t][u], ah4[t], bh[u]);
                    mmabf(upc[t][u], ah4[t], bl[u]);
                    mmabf(upc[t][u], al4[t], bh[u]);
                }
        }
        // gate GEMM: wg limbs
        {
            uint32_t bh[4][2], bl[4][2];
#pragma unroll
            for (int u = 0; u < 4; ++u) {
                const int nr = (wn * 32 + u * 8 + ar) * ROWB;
                bh[u][0] = *(const uint32_t*)(st + 18432 + nr + koA);
                bh[u][1] = *(const uint32_t*)(st + 18432 + nr + koA + 16);
                bl[u][0] = *(const uint32_t*)(st + 21504 + nr + koA);
                bl[u][1] = *(const uint32_t*)(st + 21504 + nr + koA + 16);
            }
#pragma unroll
            for (int t = 0; t < 4; ++t)
#pragma unroll
                for (int u = 0; u < 4; ++u) {
                    mmabf(gtc[t][u], ah4[t], bh[u]);
                    mmabf(gtc[t][u], ah4[t], bl[u]);
                    mmabf(gtc[t][u], al4[t], bh[u]);
                }
        }
    }

    // ---------------- epilogue: band recompute + mask + silu -> act limbs ---
#pragma unroll
    for (int t = 0; t < 4; ++t) {
#pragma unroll
        for (int u = 0; u < 4; ++u) {
            const int gr = m0 + wm * 64 + t * 16 + ar;
            const int gc = n0 + wn * 32 + u * 8 + 2 * ac;
            const float a0 = __ldg(ag + gc), a1 = __ldg(ag + gc + 1);
            float uv[4] = {upc[t][u][0], upc[t][u][1], upc[t][u][2], upc[t][u][3]};
            float gv[4] = {gtc[t][u][0], gtc[t][u][1], gtc[t][u][2], gtc[t][u][3]};
            float av[4] = {a0, a1, a0, a1};
            int   rw[4] = {gr, gr, gr + 8, gr + 8};
            int   cl[4] = {gc, gc + 1, gc, gc + 1};
#pragma unroll
            for (int q = 0; q < 4; ++q) {
                bool flag = fabsf(fabsf(uv[q] * av[q]) - TH) < BAND;
                unsigned bal = __ballot_sync(0xffffffffu, flag);
                while (bal) {
                    int src = __ffs(bal) - 1; bal &= bal - 1;
                    int rr = __shfl_sync(0xffffffffu, rw[q], src);
                    int cc = __shfl_sync(0xffffffffu, cl[q], src);
                    float s = warp_dot(x_orig + (size_t)rr * HDIM,
                                       wu_orig + (size_t)cc * HDIM, lane);
                    if (lane == src) uv[q] = s;
                }
            }
            float r0 = masked_silu(uv[0], gv[0], av[0]);
            float r1 = masked_silu(uv[1], gv[1], av[1]);
            float r2 = masked_silu(uv[2], gv[2], av[2]);
            float r3 = masked_silu(uv[3], gv[3], av[3]);
            __nv_bfloat16 h0, h1, h2, h3, l0, l1, l2, l3;
            bsplit(r0, h0, l0); bsplit(r1, h1, l1);
            bsplit(r2, h2, l2); bsplit(r3, h3, l3);
            *(uint32_t*)&g_ah[(size_t)gr * IDIM + gc]       = bpack(h0, h1);
            *(uint32_t*)&g_al[(size_t)gr * IDIM + gc]       = bpack(l0, l1);
            *(uint32_t*)&g_ah[(size_t)(gr + 8) * IDIM + gc] = bpack(h2, h3);
            *(uint32_t*)&g_al[(size_t)(gr + 8) * IDIM + gc] = bpack(l2, l3);
        }
    }
}

// ---------------------------------------------------------------------------
// P2: out = act @ wd^T, bf16 2-limb. CTA 128x128, 4 warps (2x2) @ 64x64.
// KT=16, 4-stage, 2 CTAs/SM.
// smem: act_hi[0,128) act_lo[128,256) wd_hi[256,384) wd_lo[384,512)
// ---------------------------------------------------------------------------
#define P2_STAGE (512 * ROWB)       // 24576
#define P2_SMEM  (NSTG * P2_STAGE)  // 98304

__global__ __launch_bounds__(128, 2)
void p2_kernel(float* __restrict__ out)
{
    extern __shared__ char smc[];
    const uint32_t sb = smem_u32(smc);

    const int per = 16 * 32;
    const int grp = blockIdx.x / per;
    const int w   = blockIdx.x % per;
    const int m0  = (grp * 16 + (w % 16)) * 128;
    const int n0  = (w / 16) * 128;

    const int tid  = threadIdx.x;
    const int wid  = tid >> 5;
    const int lane = tid & 31;
    const int wm   = wid >> 1;      // 0..1 (M, 64 rows)
    const int wn   = wid & 1;       // 0..1 (N, 64 cols)
    const int ar   = lane >> 2;
    const int ac   = lane & 3;
    const int koA  = 4 * ac;

    float acc[4][8][4];
#pragma unroll
    for (int t = 0; t < 4; ++t)
#pragma unroll
        for (int u = 0; u < 8; ++u)
#pragma unroll
            for (int q = 0; q < 4; ++q) acc[t][u][q] = 0.f;

    const int NCH = IDIM / KT;      // 896

    auto load_chunk = [&](int ch) {
        const uint32_t so = sb + (uint32_t)((ch & (NSTG - 1)) * P2_STAGE);
        const int kb = ch * KT;
#pragma unroll
        for (int q = 0; q < 8; ++q) {
            int lin  = q * 128 + tid;
            int gran = lin >> 9;
            int prow = lin & 511;
            const __nv_bfloat16* p;
            size_t roff;
            if (prow < 128)      { p = g_ah;  roff = (size_t)(m0 + prow) * IDIM; }
            else if (prow < 256) { p = g_al;  roff = (size_t)(m0 + prow - 128) * IDIM; }
            else if (prow < 384) { p = g_wdh; roff = (size_t)(n0 + prow - 256) * IDIM; }
            else                 { p = g_wdl; roff = (size_t)(n0 + prow - 384) * IDIM; }
            cp_async16(so + (uint32_t)(prow * ROWB + gran * 16),
                       p + roff + kb + gran * 8);
        }
        cp_commit();
    };

    load_chunk(0);
    load_chunk(1);
    load_chunk(2);

    for (int ch = 0; ch < NCH; ++ch) {
        cp_wait<2>();
        __syncthreads();
        if (ch + 3 < NCH) load_chunk(ch + 3);
        else cp_commit();

        const char* st = smc + (ch & (NSTG - 1)) * P2_STAGE;

        uint32_t ah4[4][4], al4[4][4];
#pragma unroll
        for (int t = 0; t < 4; ++t) {
            const int r0 = (wm * 64 + t * 16 + ar) * ROWB;
            const int r1 = r0 + 8 * ROWB;
            ah4[t][0] = *(const uint32_t*)(st + r0 + koA);
            ah4[t][1] = *(const uint32_t*)(st + r1 + koA);
            ah4[t][2] = *(const uint32_t*)(st + r0 + koA + 16);
            ah4[t][3] = *(const uint32_t*)(st + r1 + koA + 16);
            al4[t][0] = *(const uint32_t*)(st + 6144 + r0 + koA);
            al4[t][1] = *(const uint32_t*)(st + 6144 + r1 + koA);
            al4[t][2] = *(const uint32_t*)(st + 6144 + r0 + koA + 16);
            al4[t][3] = *(const uint32_t*)(st + 6144 + r1 + koA + 16);
        }
        uint32_t bh[8][2], bl[8][2];
#pragma unroll
        for (int u = 0; u < 8; ++u) {
            const int nr = (wn * 64 + u * 8 + ar) * ROWB;
            bh[u][0] = *(const uint32_t*)(st + 12288 + nr + koA);
            bh[u][1] = *(const uint32_t*)(st + 12288 + nr + koA + 16);
            bl[u][0] = *(const uint32_t*)(st + 18432 + nr + koA);
            bl[u][1] = *(const uint32_t*)(st + 18432 + nr + koA + 16);
        }
#pragma unroll
        for (int t = 0; t < 4; ++t)
#pragma unroll
            for (int u = 0; u < 8; ++u) {
                mmabf(acc[t][u], ah4[t], bh[u]);
                mmabf(acc[t][u], ah4[t], bl[u]);
                mmabf(acc[t][u], al4[t], bh[u]);
            }
    }

#pragma unroll
    for (int t = 0; t < 4; ++t) {
#pragma unroll
        for (int u = 0; u < 8; ++u) {
            const int gr = m0 + wm * 64 + t * 16 + ar;
            const int gc = n0 + wn * 64 + u * 8 + 2 * ac;
            float2 v0, v1;
            v0.x = acc[t][u][0]; v0.y = acc[t][u][1];
            v1.x = acc[t][u][2]; v1.y = acc[t][u][3];
            *(float2*)&out[(size_t)gr * HDIM + gc]       = v0;
            *(float2*)&out[(size_t)(gr + 8) * HDIM + gc] = v1;
        }
    }
}

// ---------------------------------------------------------------------------
// launch: inputs x, w_gate, w_up, w_down, avg_gate
// ---------------------------------------------------------------------------
extern "C" void kernel_launch(void* const* d_in, const int* in_sizes, int n_in,
                              void* d_out, int out_size)
{
    const float* x  = (const float*)d_in[0];
    const float* wg = (const float*)d_in[1];
    const float* wu = (const float*)d_in[2];
    const float* wd = (const float*)d_in[3];
    const float* ag = (const float*)d_in[4];
    float* out = (float*)d_out;

    // prep: split all operands into bf16 limb planes (single merged launch)
    {
        long long total = (long long)N4X + 3LL * N4W;
        int blocks = (int)((total + 255) / 256);
        prep_all<<<blocks, 256>>>(x, wg, wu, wd);
    }

    cudaFuncSetAttribute(p1_kernel, cudaFuncAttributeMaxDynamicSharedMemorySize, P1_SMEM);
    cudaFuncSetAttribute(p2_kernel, cudaFuncAttributeMaxDynamicSharedMemorySize, P2_SMEM);

    // P1: 64 m-tiles(128) x 224 n-tiles(64) = 14336 CTAs
    p1_kernel<<<14336, 128, P1_SMEM>>>(ag, x, wu);
    // P2: 64 m-tiles(128) x 32 n-tiles(128) = 2048 CTAs
    p2_kernel<<<2048, 128, P2_SMEM>>>(out);
}

// round 15
// speedup vs baseline: 2.0564x; 2.0564x over previous
#include <cuda_runtime.h>
#include <cstdint>
#include <math.h>

// ---------------------------------------------------------------------------
// Shapes (fixed): tokens T=8192, H=4096, I=14336
// ---------------------------------------------------------------------------
#define HDIM 4096
#define IDIM 14336
#define TH   0.5f
#define BAND 0.008f                 // borderline-mask band on |u*a| around TH

#define KT   32                     // k per smem chunk (32 floats = 128 B/row)

// scratch (tf32-rounded, column-pair-permuted operands) + act
__device__ float g_act[117440512ull];   // 8192 x 14336 (rounded+permuted)
__device__ float g_xr [33554432ull];    // 8192 x 4096
__device__ float g_wgr[58720256ull];    // 14336 x 4096
__device__ float g_wur[58720256ull];    // 14336 x 4096
__device__ float g_wdr[58720256ull];    // 4096 x 14336

// ---------------------------------------------------------------------------
// helpers
// ---------------------------------------------------------------------------
__device__ __forceinline__ uint32_t smem_u32(const void* p) {
    uint32_t a;
    asm("{ .reg .u64 t; cvta.to.shared.u64 t, %1; cvt.u32.u64 %0, t; }" : "=r"(a) : "l"(p));
    return a;
}
__device__ __forceinline__ float f2tf_f(float x) {   // RNA round to tf32
    uint32_t o;
    asm("cvt.rna.tf32.f32 %0, %1;" : "=r"(o) : "f"(x));
    return __uint_as_float(o);
}
__device__ __forceinline__ void cp_async16(uint32_t dst, const void* src) {
    asm volatile("cp.async.cg.shared.global [%0], [%1], 16;" :: "r"(dst), "l"(src) : "memory");
}
__device__ __forceinline__ void cp_commit() {
    asm volatile("cp.async.commit_group;" ::: "memory");
}
template <int N> __device__ __forceinline__ void cp_wait() {
    asm volatile("cp.async.wait_group %0;" :: "n"(N) : "memory");
}

// m16n8k8 tf32 mma
__device__ __forceinline__ void mma8(float* c, const uint32_t* a, const uint32_t* b) {
    asm volatile(
        "mma.sync.aligned.m16n8k8.row.col.f32.tf32.tf32.f32 "
        "{%0,%1,%2,%3}, {%4,%5,%6,%7}, {%8,%9}, {%0,%1,%2,%3};"
        : "+f"(c[0]), "+f"(c[1]), "+f"(c[2]), "+f"(c[3])
        : "r"(a[0]), "r"(a[1]), "r"(a[2]), "r"(a[3]), "r"(b[0]), "r"(b[1]));
}

__device__ __forceinline__ float masked_silu(float u, float g, float a) {
    float o = 0.f;
    if (fabsf(u * a) >= TH) o = u * (g / (1.f + expf(-g)));
    return o;
}

// exact fp32 dot(x_row, wu_row) over HDIM, warp-cooperative
__device__ __noinline__ float warp_dot(const float* __restrict__ xr,
                                       const float* __restrict__ wr, int lane) {
    const float4* x4 = (const float4*)xr;
    const float4* w4 = (const float4*)wr;
    float s = 0.f;
#pragma unroll 4
    for (int i = lane; i < HDIM / 4; i += 32) {
        float4 a = x4[i], b = w4[i];
        s = fmaf(a.x, b.x, s); s = fmaf(a.y, b.y, s);
        s = fmaf(a.z, b.z, s); s = fmaf(a.w, b.w, s);
    }
#pragma unroll
    for (int off = 16; off; off >>= 1) s += __shfl_xor_sync(0xffffffffu, s, off);
    return s;
}

// ---------------------------------------------------------------------------
// prep: round to tf32 (RNA) + permute each 8-col group to [0,4,1,5,2,6,3,7].
// ---------------------------------------------------------------------------
__device__ __forceinline__ void prep_one(const float* __restrict__ src,
                                         float* __restrict__ dst, size_t i) {
    const float4* s = (const float4*)src + 2 * i;
    float4 lo = s[0], hi = s[1];
    float4 o0, o1;
    o0.x = f2tf_f(lo.x); o0.y = f2tf_f(hi.x); o0.z = f2tf_f(lo.y); o0.w = f2tf_f(hi.y);
    o1.x = f2tf_f(lo.z); o1.y = f2tf_f(hi.z); o1.z = f2tf_f(lo.w); o1.w = f2tf_f(hi.w);
    float4* d = (float4*)dst + 2 * i;
    d[0] = o0; d[1] = o1;
}

#define N8X (8192 * HDIM / 8)       // 4194304
#define N8W (IDIM * HDIM / 8)       // 7340032

__global__ __launch_bounds__(256)
void prep_all(const float* __restrict__ x,  float* __restrict__ xr,
              const float* __restrict__ wg, float* __restrict__ wgr,
              const float* __restrict__ wu, float* __restrict__ wur,
              const float* __restrict__ wd, float* __restrict__ wdr)
{
    int i = blockIdx.x * blockDim.x + threadIdx.x;
    if (i < N8X)                       prep_one(x,  xr,  (size_t)i);
    else if (i < N8X + N8W)            prep_one(wg, wgr, (size_t)(i - N8X));
    else if (i < N8X + 2 * N8W)        prep_one(wu, wur, (size_t)(i - N8X - N8W));
    else if (i < N8X + 3 * N8W)        prep_one(wd, wdr, (size_t)(i - N8X - 2 * N8W));
}

// ---------------------------------------------------------------------------
// Pad-free smem swizzle: row r holds 32 floats (128 B); granule c stored at
// physical granule c ^ (2*(r&3)).
// ---------------------------------------------------------------------------
#define ROWF 32                     // floats per smem row

// ---------------------------------------------------------------------------
// P1: up = x@wu^T, gate = x@wg^T (tf32) -> masked act (rounded+permuted)
// CTA 128x64 fused, 8 warps (4x2) @ warp 32x32. KT=32, 3-stage, 2 CTAs/SM.
// ---------------------------------------------------------------------------
#define P1_STAGE_FLOATS ((128 + 64 + 64) * ROWF)     // 8192 floats = 32768 B
#define P1_SMEM (3 * P1_STAGE_FLOATS * 4)            // 98304 B

__global__ __launch_bounds__(256, 2)
void p1_kernel(const float* __restrict__ xr, const float* __restrict__ wgr,
               const float* __restrict__ wur, const float* __restrict__ ag,
               const float* __restrict__ x_orig, const float* __restrict__ wu_orig,
               float* __restrict__ act)
{
    extern __shared__ float sm[];

    const int per = 16 * 224;                 // 16 m-tiles x 224 n-tiles
    const int grp = blockIdx.x / per;
    const int w   = blockIdx.x % per;
    const int m0  = (grp * 16 + (w % 16)) * 128;
    const int n0  = (w / 16) * 64;

    const int tid  = threadIdx.x;
    const int wid  = tid >> 5;
    const int lane = tid & 31;
    const int wm   = wid >> 1;      // 0..3 (M, 32 rows)
    const int wn   = wid & 1;       // 0..1 (N, 32 cols)
    const int ar   = lane >> 2;
    const int ac   = lane & 3;
    const int sw2  = (ar & 3) << 1; // swizzle term
    const int aci  = ac >> 1;
    const int kin  = (ac & 1) << 1;

    float upc[2][4][4];
    float gtc[2][4][4];
#pragma unroll
    for (int t = 0; t < 2; ++t)
#pragma unroll
        for (int u = 0; u < 4; ++u)
#pragma unroll
            for (int q = 0; q < 4; ++q) { upc[t][u][q] = 0.f; gtc[t][u][q] = 0.f; }

    const int NCH = HDIM / KT;      // 128

    const uint32_t sXa  = smem_u32(sm);
    const uint32_t sWua = sXa + 128 * ROWF * 4;
    const uint32_t sWga = sWua + 64 * ROWF * 4;

    auto sts_off = [](int r, int c) -> uint32_t {
        return (uint32_t)(r * 128 + ((c ^ ((r & 3) << 1)) << 4));
    };

    auto load_chunk = [&](int ch) {
        const uint32_t so = (uint32_t)((ch % 3) * P1_STAGE_FLOATS * 4);
        const float* xs  = xr  + (size_t)m0 * HDIM + ch * KT;
        const float* wus = wur + (size_t)n0 * HDIM + ch * KT;
        const float* wgs = wgr + (size_t)n0 * HDIM + ch * KT;
#pragma unroll
        for (int q = 0; q < 4; ++q) {      // x: 1024 x 16B / 256 threads
            int lin = q * 256 + tid;
            int r = lin >> 3, c = lin & 7;
            cp_async16(sXa + so + sts_off(r, c), xs + (size_t)r * HDIM + c * 4);
        }
#pragma unroll
        for (int q = 0; q < 2; ++q) {      // wu: 512 x 16B
            int lin = q * 256 + tid;
            int r = lin >> 3, c = lin & 7;
            cp_async16(sWua + so + sts_off(r, c), wus + (size_t)r * HDIM + c * 4);
        }
#pragma unroll
        for (int q = 0; q < 2; ++q) {      // wg: 512 x 16B
            int lin = q * 256 + tid;
            int r = lin >> 3, c = lin & 7;
            cp_async16(sWga + so + sts_off(r, c), wgs + (size_t)r * HDIM + c * 4);
        }
        cp_commit();
    };

    load_chunk(0);
    load_chunk(1);

    for (int ch = 0; ch < NCH; ++ch) {
        cp_wait<1>();
        __syncthreads();
        if (ch + 2 < NCH) load_chunk(ch + 2);
        else cp_commit();

        const float* base = sm + (ch % 3) * P1_STAGE_FLOATS;
        const float* sX  = base;
        const float* sWu = base + 128 * ROWF;
        const float* sWg = base + 192 * ROWF;

#pragma unroll
        for (int s8 = 0; s8 < 4; ++s8) {
            const int cl = 2 * s8 + aci;
            const int co = ((cl ^ sw2) << 2) + kin;   // swizzled column offset
            uint32_t xf[2][4];
#pragma unroll
            for (int t = 0; t < 2; ++t) {
                const int mb = wm * 32 + t * 16;
                float2 p0 = *(const float2*)&sX[(mb + ar)     * ROWF + co];
                float2 p1 = *(const float2*)&sX[(mb + ar + 8) * ROWF + co];
                xf[t][0] = __float_as_uint(p0.x);
                xf[t][1] = __float_as_uint(p1.x);
                xf[t][2] = __float_as_uint(p0.y);
                xf[t][3] = __float_as_uint(p1.y);
            }
            uint32_t uf[4][2], gf[4][2];
#pragma unroll
            for (int u = 0; u < 4; ++u) {
                const int nb = wn * 32 + u * 8;
                float2 pu = *(const float2*)&sWu[(nb + ar) * ROWF + co];
                float2 pg = *(const float2*)&sWg[(nb + ar) * ROWF + co];
                uf[u][0] = __float_as_uint(pu.x); uf[u][1] = __float_as_uint(pu.y);
                gf[u][0] = __float_as_uint(pg.x); gf[u][1] = __float_as_uint(pg.y);
            }
#pragma unroll
            for (int t = 0; t < 2; ++t)
#pragma unroll
                for (int u = 0; u < 4; ++u) {
                    mma8(upc[t][u], xf[t], uf[u]);
                    mma8(gtc[t][u], xf[t], gf[u]);
                }
        }
    }

    // ---------------- epilogue: borderline recompute + mask + silu ----------
    const int pA = (ac < 2) ? 4 * ac : 4 * ac - 7;      // phys of logical 2*ac
    const int pB = (ac < 2) ? 4 * ac + 2 : 4 * ac - 5;  // phys of logical 2*ac+1
#pragma unroll
    for (int t = 0; t < 2; ++t) {
#pragma unroll
        for (int u = 0; u < 4; ++u) {
            const int gr = m0 + wm * 32 + t * 16 + ar;
            const int gb = n0 + wn * 32 + u * 8;        // 8-aligned group base
            const int gc = gb + 2 * ac;                 // logical column
            const float a0 = __ldg(ag + gc);
            const float a1 = __ldg(ag + gc + 1);
            float uv[4] = {upc[t][u][0], upc[t][u][1], upc[t][u][2], upc[t][u][3]};
            float gv[4] = {gtc[t][u][0], gtc[t][u][1], gtc[t][u][2], gtc[t][u][3]};
            float av[4] = {a0, a1, a0, a1};
            int   rw[4] = {gr, gr, gr + 8, gr + 8};
            int   cl4[4] = {gc, gc + 1, gc, gc + 1};
#pragma unroll
            for (int q = 0; q < 4; ++q) {
                bool flag = fabsf(fabsf(uv[q] * av[q]) - TH) < BAND;
                unsigned bal = __ballot_sync(0xffffffffu, flag);
                while (bal) {
                    int src = __ffs(bal) - 1; bal &= bal - 1;
                    int rr = __shfl_sync(0xffffffffu, rw[q], src);
                    int cc = __shfl_sync(0xffffffffu, cl4[q], src);
                    float s = warp_dot(x_orig + (size_t)rr * HDIM,
                                       wu_orig + (size_t)cc * HDIM, lane);
                    if (lane == src) uv[q] = s;
                }
            }
            float r0 = f2tf_f(masked_silu(uv[0], gv[0], av[0]));
            float r1 = f2tf_f(masked_silu(uv[1], gv[1], av[1]));
            float r2 = f2tf_f(masked_silu(uv[2], gv[2], av[2]));
            float r3 = f2tf_f(masked_silu(uv[3], gv[3], av[3]));
            float* row0 = &act[(size_t)gr * IDIM + gb];
            float* row1 = &act[(size_t)(gr + 8) * IDIM + gb];
            row0[pA] = r0; row0[pB] = r1;
            row1[pA] = r2; row1[pB] = r3;
        }
    }
}

// ---------------------------------------------------------------------------
// P2: out = act @ wd^T (tf32, pre-rounded+permuted)
// CTA 128x128, 8 warps (4x2) @ warp 32x64. KT=32, 3-stage, 2 CTAs/SM.
// ---------------------------------------------------------------------------
#define P2_STAGE_FLOATS ((128 + 128) * ROWF)         // 8192 floats = 32768 B
#define P2_SMEM (3 * P2_STAGE_FLOATS * 4)            // 98304 B

__global__ __launch_bounds__(256, 2)
void p2_kernel(const float* __restrict__ act, const float* __restrict__ wdr,
               float* __restrict__ out)
{
    extern __shared__ float sm[];

    const int per = 16 * 32;                  // 16 m-tiles x 32 n-tiles
    const int grp = blockIdx.x / per;
    const int w   = blockIdx.x % per;
    const int m0  = (grp * 16 + (w % 16)) * 128;
    const int n0  = (w / 16) * 128;

    const int tid  = threadIdx.x;
    const int wid  = tid >> 5;
    const int lane = tid & 31;
    const int wm   = wid >> 1;      // 0..3 (M, 32 rows)
    const int wn   = wid & 1;       // 0..1 (N, 64 cols)
    const int ar   = lane >> 2;
    const int ac   = lane & 3;
    const int sw2  = (ar & 3) << 1;
    const int aci  = ac >> 1;
    const int kin  = (ac & 1) << 1;

    float acc[2][8][4];
#pragma unroll
    for (int t = 0; t < 2; ++t)
#pragma unroll
        for (int u = 0; u < 8; ++u)
#pragma unroll
            for (int q = 0; q < 4; ++q) acc[t][u][q] = 0.f;

    const int NCH = IDIM / KT;      // 448

    const uint32_t sAa = smem_u32(sm);
    const uint32_t sBa = sAa + 128 * ROWF * 4;

    auto sts_off = [](int r, int c) -> uint32_t {
        return (uint32_t)(r * 128 + ((c ^ ((r & 3) << 1)) << 4));
    };

    auto load_chunk = [&](int ch) {
        const uint32_t so = (uint32_t)((ch % 3) * P2_STAGE_FLOATS * 4);
        const float* as = act + (size_t)m0 * IDIM + ch * KT;
        const float* bs = wdr + (size_t)n0 * IDIM + ch * KT;
#pragma unroll
        for (int q = 0; q < 4; ++q) {      // A: 1024 x 16B / 256 threads
            int lin = q * 256 + tid;
            int r = lin >> 3, c = lin & 7;
            cp_async16(sAa + so + sts_off(r, c), as + (size_t)r * IDIM + c * 4);
        }
#pragma unroll
        for (int q = 0; q < 4; ++q) {      // B: 1024 x 16B
            int lin = q * 256 + tid;
            int r = lin >> 3, c = lin & 7;
            cp_async16(sBa + so + sts_off(r, c), bs + (size_t)r * IDIM + c * 4);
        }
        cp_commit();
    };

    load_chunk(0);
    load_chunk(1);

    for (int ch = 0; ch < NCH; ++ch) {
        cp_wait<1>();
        __syncthreads();
        if (ch + 2 < NCH) load_chunk(ch + 2);
        else cp_commit();

        const float* base = sm + (ch % 3) * P2_STAGE_FLOATS;
        const float* sA = base;
        const float* sB = base + 128 * ROWF;

#pragma unroll
        for (int s8 = 0; s8 < 4; ++s8) {
            const int cl = 2 * s8 + aci;
            const int co = ((cl ^ sw2) << 2) + kin;
            uint32_t af[2][4];
#pragma unroll
            for (int t = 0; t < 2; ++t) {
                const int mb = wm * 32 + t * 16;
                float2 p0 = *(const float2*)&sA[(mb + ar)     * ROWF + co];
                float2 p1 = *(const float2*)&sA[(mb + ar + 8) * ROWF + co];
                af[t][0] = __float_as_uint(p0.x);
                af[t][1] = __float_as_uint(p1.x);
                af[t][2] = __float_as_uint(p0.y);
                af[t][3] = __float_as_uint(p1.y);
            }
            uint32_t bf[8][2];
#pragma unroll
            for (int u = 0; u < 8; ++u) {
                const int nb = wn * 64 + u * 8;
                float2 pb = *(const float2*)&sB[(nb + ar) * ROWF + co];
                bf[u][0] = __float_as_uint(pb.x);
                bf[u][1] = __float_as_uint(pb.y);
            }
#pragma unroll
            for (int t = 0; t < 2; ++t)
#pragma unroll
                for (int u = 0; u < 8; ++u)
                    mma8(acc[t][u], af[t], bf[u]);
        }
    }

#pragma unroll
    for (int t = 0; t < 2; ++t) {
#pragma unroll
        for (int u = 0; u < 8; ++u) {
            const int gr = m0 + wm * 32 + t * 16 + ar;
            const int gc = n0 + wn * 64 + u * 8 + 2 * ac;
            float2 v0, v1;
            v0.x = acc[t][u][0]; v0.y = acc[t][u][1];
            v1.x = acc[t][u][2]; v1.y = acc[t][u][3];
            *(float2*)&out[(size_t)gr * HDIM + gc]       = v0;
            *(float2*)&out[(size_t)(gr + 8) * HDIM + gc] = v1;
        }
    }
}

// ---------------------------------------------------------------------------
// launch: inputs x, w_gate, w_up, w_down, avg_gate
// ---------------------------------------------------------------------------
extern "C" void kernel_launch(void* const* d_in, const int* in_sizes, int n_in,
                              void* d_out, int out_size)
{
    const float* x  = (const float*)d_in[0];
    const float* wg = (const float*)d_in[1];
    const float* wu = (const float*)d_in[2];
    const float* wd = (const float*)d_in[3];
    const float* ag = (const float*)d_in[4];
    float* out = (float*)d_out;

    float *act, *xr, *wgr, *wur, *wdr;
    cudaGetSymbolAddress((void**)&act, g_act);
    cudaGetSymbolAddress((void**)&xr,  g_xr);
    cudaGetSymbolAddress((void**)&wgr, g_wgr);
    cudaGetSymbolAddress((void**)&wur, g_wur);
    cudaGetSymbolAddress((void**)&wdr, g_wdr);

    // prep: round+permute all GEMM operands (single merged launch)
    {
        long long total = (long long)N8X + 3LL * N8W;
        int blocks = (int)((total + 255) / 256);
        prep_all<<<blocks, 256>>>(x, xr, wg, wgr, wu, wur, wd, wdr);
    }

    cudaFuncSetAttribute(p1_kernel, cudaFuncAttributeMaxDynamicSharedMemorySize, P1_SMEM);
    cudaFuncSetAttribute(p2_kernel, cudaFuncAttributeMaxDynamicSharedMemorySize, P2_SMEM);

    // P1: 64 m-tiles x 224 n-tiles = 14336 CTAs
    p1_kernel<<<14336, 256, P1_SMEM>>>(xr, wgr, wur, ag, x, wu, act);
    // P2: 64 m-tiles x 32 n-tiles = 2048 CTAs
    p2_kernel<<<2048, 256, P2_SMEM>>>(act, wdr, out);
}

// round 16
// speedup vs baseline: 2.3821x; 1.1584x over previous
#include <cuda_runtime.h>
#include <cstdint>
#include <math.h>

// ---------------------------------------------------------------------------
// Shapes (fixed): tokens T=8192, H=4096, I=14336
// ---------------------------------------------------------------------------
#define HDIM 4096
#define IDIM 14336
#define TH   0.5f
#define BAND 0.004f                 // borderline-mask band on |u*a| around TH

#define KT   32                     // k per smem chunk (32 floats = 128 B/row)

// scratch (tf32-rounded, column-pair-permuted operands) + act
__device__ float g_act[117440512ull];   // 8192 x 14336 (rounded+permuted)
__device__ float g_xr [33554432ull];    // 8192 x 4096
__device__ float g_wgr[58720256ull];    // 14336 x 4096
__device__ float g_wur[58720256ull];    // 14336 x 4096
__device__ float g_wdr[58720256ull];    // 4096 x 14336

// ---------------------------------------------------------------------------
// helpers
// ---------------------------------------------------------------------------
__device__ __forceinline__ uint32_t smem_u32(const void* p) {
    uint32_t a;
    asm("{ .reg .u64 t; cvta.to.shared.u64 t, %1; cvt.u32.u64 %0, t; }" : "=r"(a) : "l"(p));
    return a;
}
__device__ __forceinline__ float f2tf_f(float x) {   // RNA round to tf32
    uint32_t o;
    asm("cvt.rna.tf32.f32 %0, %1;" : "=r"(o) : "f"(x));
    return __uint_as_float(o);
}
__device__ __forceinline__ void cp_async16(uint32_t dst, const void* src) {
    asm volatile("cp.async.cg.shared.global [%0], [%1], 16;" :: "r"(dst), "l"(src) : "memory");
}
__device__ __forceinline__ void cp_commit() {
    asm volatile("cp.async.commit_group;" ::: "memory");
}
template <int N> __device__ __forceinline__ void cp_wait() {
    asm volatile("cp.async.wait_group %0;" :: "n"(N) : "memory");
}

// m16n8k8 tf32 mma
__device__ __forceinline__ void mma8(float* c, const uint32_t* a, const uint32_t* b) {
    asm volatile(
        "mma.sync.aligned.m16n8k8.row.col.f32.tf32.tf32.f32 "
        "{%0,%1,%2,%3}, {%4,%5,%6,%7}, {%8,%9}, {%0,%1,%2,%3};"
        : "+f"(c[0]), "+f"(c[1]), "+f"(c[2]), "+f"(c[3])
        : "r"(a[0]), "r"(a[1]), "r"(a[2]), "r"(a[3]), "r"(b[0]), "r"(b[1]));
}

__device__ __forceinline__ float masked_silu(float u, float g, float a) {
    float o = 0.f;
    if (fabsf(u * a) >= TH) o = u * (g / (1.f + expf(-g)));
    return o;
}

// exact fp32 dot(x_row, wu_row) over HDIM, warp-cooperative
__device__ __noinline__ float warp_dot(const float* __restrict__ xr,
                                       const float* __restrict__ wr, int lane) {
    const float4* x4 = (const float4*)xr;
    const float4* w4 = (const float4*)wr;
    float s = 0.f;
#pragma unroll 4
    for (int i = lane; i < HDIM / 4; i += 32) {
        float4 a = x4[i], b = w4[i];
        s = fmaf(a.x, b.x, s); s = fmaf(a.y, b.y, s);
        s = fmaf(a.z, b.z, s); s = fmaf(a.w, b.w, s);
    }
#pragma unroll
    for (int off = 16; off; off >>= 1) s += __shfl_xor_sync(0xffffffffu, s, off);
    return s;
}

// ---------------------------------------------------------------------------
// prep: round to tf32 (RNA) + permute each 8-col group to [0,4,1,5,2,6,3,7].
// Single merged launch covering x + wg + wu + wd.
// ---------------------------------------------------------------------------
__device__ __forceinline__ void prep_one(const float* __restrict__ src,
                                         float* __restrict__ dst, size_t i) {
    const float4* s = (const float4*)src + 2 * i;
    float4 lo = s[0], hi = s[1];
    float4 o0, o1;
    o0.x = f2tf_f(lo.x); o0.y = f2tf_f(hi.x); o0.z = f2tf_f(lo.y); o0.w = f2tf_f(hi.y);
    o1.x = f2tf_f(lo.z); o1.y = f2tf_f(hi.z); o1.z = f2tf_f(lo.w); o1.w = f2tf_f(hi.w);
    float4* d = (float4*)dst + 2 * i;
    d[0] = o0; d[1] = o1;
}

#define N8X (8192 * HDIM / 8)       // 4194304
#define N8W (IDIM * HDIM / 8)       // 7340032

__global__ __launch_bounds__(256)
void prep_all(const float* __restrict__ x,  float* __restrict__ xr,
              const float* __restrict__ wg, float* __restrict__ wgr,
              const float* __restrict__ wu, float* __restrict__ wur,
              const float* __restrict__ wd, float* __restrict__ wdr)
{
    int i = blockIdx.x * blockDim.x + threadIdx.x;
    if (i < N8X)                       prep_one(x,  xr,  (size_t)i);
    else if (i < N8X + N8W)            prep_one(wg, wgr, (size_t)(i - N8X));
    else if (i < N8X + 2 * N8W)        prep_one(wu, wur, (size_t)(i - N8X - N8W));
    else if (i < N8X + 3 * N8W)        prep_one(wd, wdr, (size_t)(i - N8X - 2 * N8W));
}

// ---------------------------------------------------------------------------
// Pad-free smem swizzle: tile row r holds 32 floats (128 B). 16B granule c
// (0..7) stored at physical granule c ^ (2*(r&3)).
// ---------------------------------------------------------------------------
#define ROWF 32                     // floats per smem row

// ---------------------------------------------------------------------------
// P1: up = x@wu^T (tf32), gate = x@wg^T (tf32) -> masked act (rounded+permuted)
// CTA 128x64 fused, 4 warps (2x2) @ 64x32. KT=32, 3-stage, 2 CTAs/SM.
// ---------------------------------------------------------------------------
#define P1_STAGE_FLOATS ((128 + 64 + 64) * ROWF)     // 8192 floats = 32768 B
#define P1_SMEM (3 * P1_STAGE_FLOATS * 4)            // 98304 B

__global__ __launch_bounds__(128, 2)
void p1_kernel(const float* __restrict__ xr, const float* __restrict__ wgr,
               const float* __restrict__ wur, const float* __restrict__ ag,
               const float* __restrict__ x_orig, const float* __restrict__ wu_orig,
               float* __restrict__ act)
{
    extern __shared__ float sm[];

    const int per = 16 * 224;                 // 16 m-tiles x 224 n-tiles
    const int grp = blockIdx.x / per;
    const int w   = blockIdx.x % per;
    const int m0  = (grp * 16 + (w % 16)) * 128;
    const int n0  = (w / 16) * 64;

    const int tid  = threadIdx.x;
    const int wid  = tid >> 5;
    const int lane = tid & 31;
    const int wm   = wid >> 1;      // 0..1 (M, 64 rows)
    const int wn   = wid & 1;       // 0..1 (N, 32 cols)
    const int ar   = lane >> 2;
    const int ac   = lane & 3;
    const int sw2  = (ar & 3) << 1; // swizzle term
    const int aci  = ac >> 1;
    const int kin  = (ac & 1) << 1;

    float upc[4][4][4];
    float gtc[4][4][4];
#pragma unroll
    for (int t = 0; t < 4; ++t)
#pragma unroll
        for (int u = 0; u < 4; ++u)
#pragma unroll
            for (int q = 0; q < 4; ++q) { upc[t][u][q] = 0.f; gtc[t][u][q] = 0.f; }

    const int NCH = HDIM / KT;      // 128

    const uint32_t sXa  = smem_u32(sm);
    const uint32_t sWua = sXa + 128 * ROWF * 4;
    const uint32_t sWga = sWua + 64 * ROWF * 4;

    auto sts_off = [](int r, int c) -> uint32_t {
        return (uint32_t)(r * 128 + ((c ^ ((r & 3) << 1)) << 4));
    };

    auto load_chunk = [&](int ch) {
        const uint32_t so = (uint32_t)((ch % 3) * P1_STAGE_FLOATS * 4);
        const float* xs  = xr  + (size_t)m0 * HDIM + ch * KT;
        const float* wus = wur + (size_t)n0 * HDIM + ch * KT;
        const float* wgs = wgr + (size_t)n0 * HDIM + ch * KT;
#pragma unroll
        for (int q = 0; q < 8; ++q) {      // x: 1024 x 16B / 128 threads
            int lin = q * 128 + tid;
            int r = lin >> 3, c = lin & 7;
            cp_async16(sXa + so + sts_off(r, c), xs + (size_t)r * HDIM + c * 4);
        }
#pragma unroll
        for (int q = 0; q < 4; ++q) {      // wu: 512 x 16B
            int lin = q * 128 + tid;
            int r = lin >> 3, c = lin & 7;
            cp_async16(sWua + so + sts_off(r, c), wus + (size_t)r * HDIM + c * 4);
        }
#pragma unroll
        for (int q = 0; q < 4; ++q) {      // wg: 512 x 16B
            int lin = q * 128 + tid;
            int r = lin >> 3, c = lin & 7;
            cp_async16(sWga + so + sts_off(r, c), wgs + (size_t)r * HDIM + c * 4);
        }
        cp_commit();
    };

    load_chunk(0);
    load_chunk(1);

    for (int ch = 0; ch < NCH; ++ch) {
        cp_wait<1>();                       // chunk ch ready; ch+1 may be in flight
        __syncthreads();
        if (ch + 2 < NCH) load_chunk(ch + 2);
        else cp_commit();                   // empty group keeps wait<1> invariant

        const float* base = sm + (ch % 3) * P1_STAGE_FLOATS;
        const float* sX  = base;
        const float* sWu = base + 128 * ROWF;
        const float* sWg = base + 192 * ROWF;

#pragma unroll
        for (int s8 = 0; s8 < 4; ++s8) {
            const int cl = 2 * s8 + aci;
            const int co = ((cl ^ sw2) << 2) + kin;   // swizzled column offset
            uint32_t xf[4][4];
#pragma unroll
            for (int t = 0; t < 4; ++t) {
                const int mb = wm * 64 + t * 16;
                float2 p0 = *(const float2*)&sX[(mb + ar)     * ROWF + co];
                float2 p1 = *(const float2*)&sX[(mb + ar + 8) * ROWF + co];
                xf[t][0] = __float_as_uint(p0.x);
                xf[t][1] = __float_as_uint(p1.x);
                xf[t][2] = __float_as_uint(p0.y);
                xf[t][3] = __float_as_uint(p1.y);
            }
            uint32_t uf[4][2], gf[4][2];
#pragma unroll
            for (int u = 0; u < 4; ++u) {
                const int nb = wn * 32 + u * 8;
                float2 pu = *(const float2*)&sWu[(nb + ar) * ROWF + co];
                float2 pg = *(const float2*)&sWg[(nb + ar) * ROWF + co];
                uf[u][0] = __float_as_uint(pu.x); uf[u][1] = __float_as_uint(pu.y);
                gf[u][0] = __float_as_uint(pg.x); gf[u][1] = __float_as_uint(pg.y);
            }
#pragma unroll
            for (int t = 0; t < 4; ++t)
#pragma unroll
                for (int u = 0; u < 4; ++u) {
                    mma8(upc[t][u], xf[t], uf[u]);
                    mma8(gtc[t][u], xf[t], gf[u]);
                }
        }
    }

    // ---------------- epilogue: borderline recompute + mask + silu ----------
    const int pA = (ac < 2) ? 4 * ac : 4 * ac - 7;      // phys of logical 2*ac
    const int pB = (ac < 2) ? 4 * ac + 2 : 4 * ac - 5;  // phys of logical 2*ac+1
#pragma unroll
    for (int t = 0; t < 4; ++t) {
#pragma unroll
        for (int u = 0; u < 4; ++u) {
            const int gr = m0 + wm * 64 + t * 16 + ar;
            const int gb = n0 + wn * 32 + u * 8;        // 8-aligned group base
            const int gc = gb + 2 * ac;                 // logical column
            const float a0 = __ldg(ag + gc);
            const float a1 = __ldg(ag + gc + 1);
            float uv[4] = {upc[t][u][0], upc[t][u][1], upc[t][u][2], upc[t][u][3]};
            float gv[4] = {gtc[t][u][0], gtc[t][u][1], gtc[t][u][2], gtc[t][u][3]};
            float av[4] = {a0, a1, a0, a1};
            int   rw[4] = {gr, gr, gr + 8, gr + 8};
            int   cl4[4] = {gc, gc + 1, gc, gc + 1};
#pragma unroll
            for (int q = 0; q < 4; ++q) {
                bool flag = fabsf(fabsf(uv[q] * av[q]) - TH) < BAND;
                unsigned bal = __ballot_sync(0xffffffffu, flag);
                while (bal) {
                    int src = __ffs(bal) - 1; bal &= bal - 1;
                    int rr = __shfl_sync(0xffffffffu, rw[q], src);
                    int cc = __shfl_sync(0xffffffffu, cl4[q], src);
                    float s = warp_dot(x_orig + (size_t)rr * HDIM,
                                       wu_orig + (size_t)cc * HDIM, lane);
                    if (lane == src) uv[q] = s;
                }
            }
            float r0 = f2tf_f(masked_silu(uv[0], gv[0], av[0]));
            float r1 = f2tf_f(masked_silu(uv[1], gv[1], av[1]));
            float r2 = f2tf_f(masked_silu(uv[2], gv[2], av[2]));
            float r3 = f2tf_f(masked_silu(uv[3], gv[3], av[3]));
            float* row0 = &act[(size_t)gr * IDIM + gb];
            float* row1 = &act[(size_t)(gr + 8) * IDIM + gb];
            row0[pA] = r0; row0[pB] = r1;
            row1[pA] = r2; row1[pB] = r3;
        }
    }
}

// ---------------------------------------------------------------------------
// P2: out = act @ wd^T (tf32, pre-rounded+permuted)
// CTA 128x128, 4 warps (2x2) @ 64x64. KT=32, 3-stage, 2 CTAs/SM.
// ---------------------------------------------------------------------------
#define P2_STAGE_FLOATS ((128 + 128) * ROWF)         // 8192 floats = 32768 B
#define P2_SMEM (3 * P2_STAGE_FLOATS * 4)            // 98304 B

__global__ __launch_bounds__(128, 2)
void p2_kernel(const float* __restrict__ act, const float* __restrict__ wdr,
               float* __restrict__ out)
{
    extern __shared__ float sm[];

    const int per = 16 * 32;                  // 16 m-tiles x 32 n-tiles
    const int grp = blockIdx.x / per;
    const int w   = blockIdx.x % per;
    const int m0  = (grp * 16 + (w % 16)) * 128;
    const int n0  = (w / 16) * 128;

    const int tid  = threadIdx.x;
    const int wid  = tid >> 5;
    const int lane = tid & 31;
    const int wm   = wid >> 1;      // 0..1 (M, 64 rows)
    const int wn   = wid & 1;       // 0..1 (N, 64 cols)
    const int ar   = lane >> 2;
    const int ac   = lane & 3;
    const int sw2  = (ar & 3) << 1;
    const int aci  = ac >> 1;
    const int kin  = (ac & 1) << 1;

    float acc[4][8][4];
#pragma unroll
    for (int t = 0; t < 4; ++t)
#pragma unroll
        for (int u = 0; u < 8; ++u)
#pragma unroll
            for (int q = 0; q < 4; ++q) acc[t][u][q] = 0.f;

    const int NCH = IDIM / KT;      // 448

    const uint32_t sAa = smem_u32(sm);
    const uint32_t sBa = sAa + 128 * ROWF * 4;

    auto sts_off = [](int r, int c) -> uint32_t {
        return (uint32_t)(r * 128 + ((c ^ ((r & 3) << 1)) << 4));
    };

    auto load_chunk = [&](int ch) {
        const uint32_t so = (uint32_t)((ch % 3) * P2_STAGE_FLOATS * 4);
        const float* as = act + (size_t)m0 * IDIM + ch * KT;
        const float* bs = wdr + (size_t)n0 * IDIM + ch * KT;
#pragma unroll
        for (int q = 0; q < 8; ++q) {      // A: 1024 x 16B / 128 threads
            int lin = q * 128 + tid;
            int r = lin >> 3, c = lin & 7;
            cp_async16(sAa + so + sts_off(r, c), as + (size_t)r * IDIM + c * 4);
        }
#pragma unroll
        for (int q = 0; q < 8; ++q) {      // B: 1024 x 16B
            int lin = q * 128 + tid;
            int r = lin >> 3, c = lin & 7;
            cp_async16(sBa + so + sts_off(r, c), bs + (size_t)r * IDIM + c * 4);
        }
        cp_commit();
    };

    load_chunk(0);
    load_chunk(1);

    for (int ch = 0; ch < NCH; ++ch) {
        cp_wait<1>();
        __syncthreads();
        if (ch + 2 < NCH) load_chunk(ch + 2);
        else cp_commit();

        const float* base = sm + (ch % 3) * P2_STAGE_FLOATS;
        const float* sA = base;
        const float* sB = base + 128 * ROWF;

#pragma unroll
        for (int s8 = 0; s8 < 4; ++s8) {
            const int cl = 2 * s8 + aci;
            const int co = ((cl ^ sw2) << 2) + kin;
            uint32_t af[4][4];
#pragma unroll
            for (int t = 0; t < 4; ++t) {
                const int mb = wm * 64 + t * 16;
                float2 p0 = *(const float2*)&sA[(mb + ar)     * ROWF + co];
                float2 p1 = *(const float2*)&sA[(mb + ar + 8) * ROWF + co];
                af[t][0] = __float_as_uint(p0.x);
                af[t][1] = __float_as_uint(p1.x);
                af[t][2] = __float_as_uint(p0.y);
                af[t][3] = __float_as_uint(p1.y);
            }
            uint32_t bf[8][2];
#pragma unroll
            for (int u = 0; u < 8; ++u) {
                const int nb = wn * 64 + u * 8;
                float2 pb = *(const float2*)&sB[(nb + ar) * ROWF + co];
                bf[u][0] = __float_as_uint(pb.x);
                bf[u][1] = __float_as_uint(pb.y);
            }
#pragma unroll
            for (int t = 0; t < 4; ++t)
#pragma unroll
                for (int u = 0; u < 8; ++u)
                    mma8(acc[t][u], af[t], bf[u]);
        }
    }

#pragma unroll
    for (int t = 0; t < 4; ++t) {
#pragma unroll
        for (int u = 0; u < 8; ++u) {
            const int gr = m0 + wm * 64 + t * 16 + ar;
            const int gc = n0 + wn * 64 + u * 8 + 2 * ac;
            float2 v0, v1;
            v0.x = acc[t][u][0]; v0.y = acc[t][u][1];
            v1.x = acc[t][u][2]; v1.y = acc[t][u][3];
            *(float2*)&out[(size_t)gr * HDIM + gc]       = v0;
            *(float2*)&out[(size_t)(gr + 8) * HDIM + gc] = v1;
        }
    }
}

// ---------------------------------------------------------------------------
// launch: inputs x, w_gate, w_up, w_down, avg_gate
// ---------------------------------------------------------------------------
extern "C" void kernel_launch(void* const* d_in, const int* in_sizes, int n_in,
                              void* d_out, int out_size)
{
    const float* x  = (const float*)d_in[0];
    const float* wg = (const float*)d_in[1];
    const float* wu = (const float*)d_in[2];
    const float* wd = (const float*)d_in[3];
    const float* ag = (const float*)d_in[4];
    float* out = (float*)d_out;

    float *act, *xr, *wgr, *wur, *wdr;
    cudaGetSymbolAddress((void**)&act, g_act);
    cudaGetSymbolAddress((void**)&xr,  g_xr);
    cudaGetSymbolAddress((void**)&wgr, g_wgr);
    cudaGetSymbolAddress((void**)&wur, g_wur);
    cudaGetSymbolAddress((void**)&wdr, g_wdr);

    // prep: round+permute all GEMM operands (single merged launch)
    {
        long long total = (long long)N8X + 3LL * N8W;
        int blocks = (int)((total + 255) / 256);
        prep_all<<<blocks, 256>>>(x, xr, wg, wgr, wu, wur, wd, wdr);
    }

    cudaFuncSetAttribute(p1_kernel, cudaFuncAttributeMaxDynamicSharedMemorySize, P1_SMEM);
    cudaFuncSetAttribute(p2_kernel, cudaFuncAttributeMaxDynamicSharedMemorySize, P2_SMEM);

    // P1: 64 m-tiles x 224 n-tiles = 14336 CTAs
    p1_kernel<<<14336, 128, P1_SMEM>>>(xr, wgr, wur, ag, x, wu, act);
    // P2: 64 m-tiles x 32 n-tiles = 2048 CTAs
    p2_kernel<<<2048, 128, P2_SMEM>>>(act, wdr, out);
}